// round 13
// baseline (speedup 1.0000x reference)
#include <cuda_runtime.h>
#include <cuda_fp16.h>
#include <cstdint>

#define BATCH 16
#define PARTIAL_OFF (BATCH * 32 * 1024)   // floats per partial buffer (524288)

// in_conv output (complete) + two ping-pong 4-partial buffers.
__device__ float g_in[PARTIAL_OFF];
__device__ float g_sp0[4 * PARTIAL_OFF];
__device__ float g_sp1[4 * PARTIAL_OFF];

// Converted weights (fp16 hi/lo split, lo pre-scaled by 2048), k-permuted:
// hidden: [20][ci 32][ky 32][h 2][co 32][kx 32], input layer appended.
#define WL_HALVES (32 * 32 * 2 * 32 * 32)
#define WIN_OFF   (20 * WL_HALVES)
__device__ __half g_wcv[20 * WL_HALVES + 32 * 2 * 32 * 32];

// Iterated circular pad (31 iters): core [31,62]->j-31; outside: even->31, odd->0.
__device__ __forceinline__ int padidx(int j) {
    return (j >= 31 && j <= 62) ? (j - 31) : ((j & 1) ? 0 : 31);
}

// k-permutation: halves {2q,2q+1,2q+8,2q+9} contiguous (one LDS.64 -> b0,b1).
__device__ __forceinline__ int kperm(int kx) {
    return (kx & 16) + 4 * ((kx & 7) >> 1) + ((kx >> 3) & 1) * 2 + (kx & 1);
}

// ---------------- weight conversion --------------------------------------
__global__ void convert_weights(const float* __restrict__ convs_w,
                                const float* __restrict__ in_w)
{
    long long i = (long long)blockIdx.x * 256 + threadIdx.x;
    const long long NH = 20ll * 32 * 32 * 32 * 32;
    if (i < NH) {
        int kx = (int)(i & 31); long long r = i >> 5;
        int co = (int)(r & 31); r >>= 5;
        int ky = (int)(r & 31); r >>= 5;
        int ci = (int)(r & 31); r >>= 5;
        int l  = (int)r;
        float v = convs_w[((((long long)l * 32 + co) * 32 + ci) * 32 + ky) * 32 + kx];
        __half h  = __float2half_rn(v);
        __half lo = __float2half_rn((v - __half2float(h)) * 2048.0f);
        long long ob = (long long)l * WL_HALVES
                     + ((((long long)ci * 32 + ky) * 2 + 0) * 32 + co) * 32 + kperm(kx);
        g_wcv[ob] = h;
        g_wcv[ob + 32 * 32] = lo;          // h-dim stride = 1024 halves
    } else {
        long long j = i - NH;
        if (j < 32 * 32 * 32) {
            int kx = (int)(j & 31); int rr = (int)(j >> 5);
            int co = rr & 31; rr >>= 5;
            int ky = rr & 31;
            float v = in_w[(co * 32 + ky) * 32 + kx];   // [co][1][ky][kx]
            __half h  = __float2half_rn(v);
            __half lo = __float2half_rn((v - __half2float(h)) * 2048.0f);
            long long ob = WIN_OFF + (((long long)ky * 2 + 0) * 32 + co) * 32 + kperm(kx);
            g_wcv[ob] = h;
            g_wcv[ob + 32 * 32] = lo;
        }
    }
}

// ---------------- mma helper ----------------------------------------------
__device__ __forceinline__ void mma16816(float* d, const uint32_t* a,
                                         uint32_t b0, uint32_t b1) {
    asm volatile(
        "mma.sync.aligned.m16n8k16.row.col.f32.f16.f16.f32 "
        "{%0,%1,%2,%3}, {%4,%5,%6,%7}, {%8,%9}, {%0,%1,%2,%3};"
        : "+f"(d[0]), "+f"(d[1]), "+f"(d[2]), "+f"(d[3])
        : "r"(a[0]), "r"(a[1]), "r"(a[2]), "r"(a[3]), "r"(b0), "r"(b1));
}

// 24 MMAs; same-accumulator writes are >= 8 issues apart (no exposed RAW).
#define MMAB(bh_, bl_) do {                                                     \
    _Pragma("unroll")                                                           \
    for (int nt_ = 0; nt_ < 4; nt_++)                                           \
        mma16816(C1 + nt_ * 4, ah0, bh_[nt_].x, bh_[nt_].y);                    \
    _Pragma("unroll")                                                           \
    for (int nt_ = 0; nt_ < 4; nt_++)                                           \
        mma16816(C1 + 16 + nt_ * 4, ah1, bh_[nt_].x, bh_[nt_].y);               \
    _Pragma("unroll")                                                           \
    for (int nt_ = 0; nt_ < 4; nt_++)                                           \
        mma16816(C2 + nt_ * 4, al0, bh_[nt_].x, bh_[nt_].y);                    \
    _Pragma("unroll")                                                           \
    for (int nt_ = 0; nt_ < 4; nt_++)                                           \
        mma16816(C2 + 16 + nt_ * 4, al1, bh_[nt_].x, bh_[nt_].y);               \
    _Pragma("unroll")                                                           \
    for (int nt_ = 0; nt_ < 4; nt_++)                                           \
        mma16816(C2 + nt_ * 4, ah0, bl_[nt_].x, bl_[nt_].y);                    \
    _Pragma("unroll")                                                           \
    for (int nt_ = 0; nt_ < 4; nt_++)                                           \
        mma16816(C2 + 16 + nt_ * 4, ah1, bl_[nt_].x, bl_[nt_].y);               \
} while (0)

// Full fragment load for one kxi step (16 LDS.32, broadcast-heavy).
#define LOADF_FULL(KXH) do {                                                    \
    _Pragma("unroll")                                                           \
    for (int i_ = 0; i_ < 4; i_++) {                                            \
        const int o_ = c0 + (KXH) + 16 * (i_ & 1) + 8 * (i_ >> 1);              \
        ah0[i_] = *(const uint32_t*)(arow + o_);                                \
        ah1[i_] = *(const uint32_t*)(arow + o_ + 32);                           \
        al0[i_] = *(const uint32_t*)(lrow + o_);                                \
        al1[i_] = *(const uint32_t*)(lrow + o_ + 32);                           \
    }                                                                           \
} while (0)

// Register permutation kxi 0 -> 1 (only 2 new words per hi/lo set).
#define SHIFT01(f0, f1, row) do {                                               \
    f0[0] = f0[1]; f0[1] = f1[0]; f0[2] = f0[3]; f0[3] = f1[2];                 \
    f1[0] = f1[1]; f1[1] = *(const uint32_t*)((row) + c0 + 64);                 \
    f1[2] = f1[3]; f1[3] = *(const uint32_t*)((row) + c0 + 72);                 \
} while (0)

// Register permutation kxi 1 -> 0 (only 2 new words per hi/lo set).
#define SHIFT10(f0, f1, row) do {                                               \
    f1[1] = f1[0]; f1[0] = f0[1]; f1[3] = f1[2]; f1[2] = f0[3];                 \
    f0[1] = f0[0]; f0[3] = f0[2];                                               \
    f0[0] = *(const uint32_t*)((row) + c0);                                     \
    f0[2] = *(const uint32_t*)((row) + c0 + 8);                                 \
} while (0)

// B fragment load + 24 MMAs for one kxi step.
#define DO_B(KXH) do {                                                          \
    const __half* bb_ = bky + (KXH);                                            \
    uint2 bh_[4], bl_[4];                                                       \
    _Pragma("unroll")                                                           \
    for (int nt_ = 0; nt_ < 4; nt_++) {                                         \
        bh_[nt_] = *(const uint2*)(bb_ + nt_ * 384);                            \
        bl_[nt_] = *(const uint2*)(bb_ + nt_ * 384 + 1536);                     \
    }                                                                           \
    MMAB(bh_, bl_);                                                             \
} while (0)

// ---------------- smem layout (halves) -------------------------------------
// Two pad buffers (hi [46][96] + lo [46][96] each), then double-buffered B.
#define PADB_H 8832                   // halves per pad buffer
#define SB_H   17664                  // B stage [2 buf][4 ky][2 h][32 co][48]
#define BUF_STRIDE 12288
#define SMEM_HALVES (17664 + 2 * BUF_STRIDE)
#define SMEM_SZ (SMEM_HALVES * 2)     // 84480 bytes -> 2 CTAs/SM fit

// One CTA: partial kk of out[b, :, oyh*8 .. +7, :]. M=256, N=32, K=NCI_H*1024.
// 8 warps; warp w owns oy row w (2 m-tiles sharing B). kk = blockIdx.z.
// kxi-paired A-fragment reuse; warps 0-3 order 0->1, warps 4-7 order 1->0;
// 4-phase kyl stagger; pad double-buffered with mid-ci prefetch.
template <int NCI_H, int NSRC, bool RELU_IN>
__global__ __launch_bounds__(256, 2)
void mma_conv(const float* __restrict__ in,
              const __half* __restrict__ wv,
              const float* __restrict__ bias,
              float* __restrict__ out)
{
    extern __shared__ __half sh[];
    __half* sB = sh + SB_H;

    const int b = blockIdx.y, oyh = blockIdx.x, kk = blockIdx.z;
    const int t = threadIdx.x, lane = t & 31, wid = t >> 5;
    const int pr0 = oyh * 16;
    constexpr int NCI_TOT = (NCI_H == 1) ? 1 : 32;

    const __half* wvk = wv + (size_t)kk * NCI_H * 65536;
    float* outk = out + (size_t)kk * PARTIAL_OFF;

    auto load_pad_to = [&](int ci, int pb) {
        __half* dH = sh + pb * PADB_H;
        __half* dL = dH + 4416;
        const float* s0 = in + (b * NCI_TOT + ci) * 1024;
        for (int k = t; k < 46 * 94; k += 256) {
            int lr = k / 94, c = k - lr * 94;
            int off = padidx(pr0 + lr) * 32 + padidx(c);
            float v = 0.0f;
            #pragma unroll
            for (int p = 0; p < NSRC; p++) v += s0[p * PARTIAL_OFF + off];
            if (RELU_IN) v = fmaxf(v, 0.0f);
            __half h = __float2half_rn(v);
            dH[lr * 96 + c] = h;
            dL[lr * 96 + c] = __float2half_rn((v - __half2float(h)) * 2048.0f);
        }
    };

    // staging: thread t owns one (ky_l, h, co) row of 32 halves (48 stride)
    __half* st_dst0 = sB + t * 48;

    constexpr int NCHUNK = NCI_H * 8;     // 4 ky per chunk

    uint4 pf[4];
    {
        const uint4* g = (const uint4*)wvk + t * 4;
        pf[0] = g[0]; pf[1] = g[1]; pf[2] = g[2]; pf[3] = g[3];
    }
    load_pad_to(kk * NCI_H, 0);
    __syncthreads();

    float C1[32] = {}, C2[32] = {};
    const int g4 = lane >> 2, q4 = lane & 3;
    const int c0 = 2 * g4 + 2 * q4;
    int pbuf = 0;

    for (int c = 0; c < NCHUNK; c++) {
        const int buf = c & 1;

        if (NCI_H > 1 && c > 0 && (c & 7) == 0) pbuf ^= 1;  // switch to prefetched pad

        {
            uint4* d = (uint4*)(st_dst0 + buf * BUF_STRIDE);
            d[0] = pf[0]; d[1] = pf[1]; d[2] = pf[2]; d[3] = pf[3];
        }
        if (c + 1 < NCHUNK) {
            const uint4* g = (const uint4*)wvk + (size_t)(c + 1) * 1024 + t * 4;
            pf[0] = g[0]; pf[1] = g[1]; pf[2] = g[2]; pf[3] = g[3];
        }
        __syncthreads();

        // mid-ci: prefetch next pad into the alternate buffer (overlaps compute;
        // visibility guaranteed by the staging barriers of chunks +1..+3)
        if (NCI_H > 1 && (c & 7) == 4 && (c >> 3) + 1 < NCI_H)
            load_pad_to(kk * NCI_H + (c >> 3) + 1, pbuf ^ 1);

        const __half* pHc = sh + pbuf * PADB_H;
        const __half* pLc = pHc + 4416;
        const int ky0 = (c & 7) * 4;

        #pragma unroll
        for (int p0 = 0; p0 < 4; p0++) {
            const int kyl = (p0 + wid) & 3;        // 4-phase kyl stagger
            const int R = 2 * wid + ky0 + kyl;
            const __half* arow = pHc + R * 96;
            const __half* lrow = pLc + R * 96;
            const __half* bky  = sB + buf * BUF_STRIDE + kyl * 3072
                               + g4 * 48 + q4 * 4;

            uint32_t ah0[4], ah1[4], al0[4], al1[4];
            if ((wid & 4) == 0) {
                LOADF_FULL(0);
                DO_B(0);
                SHIFT01(ah0, ah1, arow);
                SHIFT01(al0, al1, lrow);
                DO_B(16);
            } else {
                LOADF_FULL(16);
                DO_B(16);
                SHIFT10(ah0, ah1, arow);
                SHIFT10(al0, al1, lrow);
                DO_B(0);
            }
        }
    }

    // epilogue: raw partial sums (bias only from kk==0; ReLU at consumer)
    const int oy = oyh * 8 + wid;
    const float inv = 1.0f / 2048.0f;
    const float bs = (kk == 0) ? 1.0f : 0.0f;
    #pragma unroll
    for (int mt = 0; mt < 2; mt++) {
        const int oxa = mt * 16 + g4, oxb = oxa + 8;
        #pragma unroll
        for (int nt = 0; nt < 4; nt++) {
            const int co = nt * 8 + q4 * 2;
            const int ix = mt * 16 + nt * 4;
            const float b0v = __ldg(bias + co) * bs;
            const float b1v = __ldg(bias + co + 1) * bs;
            float v00 = C1[ix+0] + C2[ix+0] * inv + b0v;
            float v01 = C1[ix+1] + C2[ix+1] * inv + b1v;
            float v10 = C1[ix+2] + C2[ix+2] * inv + b0v;
            float v11 = C1[ix+3] + C2[ix+3] * inv + b1v;
            outk[((b * 32 + co    ) * 32 + oy) * 32 + oxa] = v00;
            outk[((b * 32 + co + 1) * 32 + oy) * 32 + oxa] = v01;
            outk[((b * 32 + co    ) * 32 + oy) * 32 + oxb] = v10;
            outk[((b * 32 + co + 1) * 32 + oy) * 32 + oxb] = v11;
        }
    }
}

// Final 1x1 conv over 4-partial input (sum + ReLU fused)
__global__ void out1x1_kernel(const float* __restrict__ h,
                              const float* __restrict__ ow,
                              const float* __restrict__ ob,
                              float* __restrict__ out)
{
    const int i = blockIdx.x * blockDim.x + threadIdx.x;
    if (i >= BATCH * 1024) return;
    const int b = i >> 10;
    const int p = i & 1023;
    const float* hp = h + b * 32 * 1024 + p;
    float acc = ob[0];
    #pragma unroll
    for (int co = 0; co < 32; co++) {
        float v = hp[co * 1024] + hp[PARTIAL_OFF + co * 1024]
                + hp[2 * PARTIAL_OFF + co * 1024] + hp[3 * PARTIAL_OFF + co * 1024];
        v = fmaxf(v, 0.0f);
        acc = fmaf(v, __ldg(ow + co), acc);
    }
    out[i] = acc;
}

extern "C" void kernel_launch(void* const* d_in, const int* in_sizes, int n_in,
                              void* d_out, int out_size)
{
    const float* x       = (const float*)d_in[0];
    const float* in_w    = (const float*)d_in[1];
    const float* in_b    = (const float*)d_in[2];
    const float* convs_w = (const float*)d_in[3];
    const float* convs_b = (const float*)d_in[4];
    const float* out_w   = (const float*)d_in[5];
    const float* out_b   = (const float*)d_in[6];

    float *gin = nullptr, *gs0 = nullptr, *gs1 = nullptr;
    __half* wcv = nullptr;
    cudaGetSymbolAddress((void**)&gin, g_in);
    cudaGetSymbolAddress((void**)&gs0, g_sp0);
    cudaGetSymbolAddress((void**)&gs1, g_sp1);
    cudaGetSymbolAddress((void**)&wcv, g_wcv);

    const long long total = 20ll * 32 * 32 * 32 * 32 + 32 * 32 * 32;
    convert_weights<<<(int)((total + 255) / 256), 256>>>(convs_w, in_w);

    cudaFuncSetAttribute(mma_conv<1, 1, false>,
                         cudaFuncAttributeMaxDynamicSharedMemorySize, SMEM_SZ);
    cudaFuncSetAttribute(mma_conv<8, 1, false>,
                         cudaFuncAttributeMaxDynamicSharedMemorySize, SMEM_SZ);
    cudaFuncSetAttribute(mma_conv<8, 4, true>,
                         cudaFuncAttributeMaxDynamicSharedMemorySize, SMEM_SZ);

    // in_conv: complete (unsplit) output, no ReLU anywhere around it
    mma_conv<1, 1, false><<<dim3(4, BATCH, 1), 256, SMEM_SZ>>>(
        x, wcv + WIN_OFF, in_b, gin);

    // hidden layer 0: reads unsplit g_in (no input ReLU), writes 4-partial gs0
    mma_conv<8, 1, false><<<dim3(4, BATCH, 4), 256, SMEM_SZ>>>(
        gin, wcv, convs_b, gs0);

    // hidden layers 1..19: read 4-partial (sum+ReLU fused), write 4-partial
    float* cur = gs0;
    float* nxt = gs1;
    for (int l = 1; l < 20; l++) {
        mma_conv<8, 4, true><<<dim3(4, BATCH, 4), 256, SMEM_SZ>>>(
            cur, wcv + (size_t)l * WL_HALVES, convs_b + l * 32, nxt);
        float* tmp = cur; cur = nxt; nxt = tmp;
    }

    // 1x1 output conv (sum partials + ReLU fused)
    out1x1_kernel<<<(BATCH * 1024) / 256, 256>>>(cur, out_w, out_b, (float*)d_out);
}

// round 14
// speedup vs baseline: 1.1970x; 1.1970x over previous
#include <cuda_runtime.h>
#include <cuda_fp16.h>
#include <cstdint>

#define BATCH 16
#define PARTIAL_OFF (BATCH * 32 * 1024)   // floats per partial buffer (524288)

// in_conv output (complete) + two ping-pong 4-partial buffers.
__device__ float g_in[PARTIAL_OFF];
__device__ float g_sp0[4 * PARTIAL_OFF];
__device__ float g_sp1[4 * PARTIAL_OFF];

// Converted weights (fp16 hi/lo split, lo pre-scaled by 2048), k-permuted:
// hidden: [20][ci 32][ky 32][h 2][co 32][kx 32], input layer appended.
#define WL_HALVES (32 * 32 * 2 * 32 * 32)
#define WIN_OFF   (20 * WL_HALVES)
__device__ __half g_wcv[20 * WL_HALVES + 32 * 2 * 32 * 32];

// Iterated circular pad (31 iters): core [31,62]->j-31; outside: even->31, odd->0.
__device__ __forceinline__ int padidx(int j) {
    return (j >= 31 && j <= 62) ? (j - 31) : ((j & 1) ? 0 : 31);
}

// k-permutation: halves {2q,2q+1,2q+8,2q+9} contiguous (one LDS.64 -> b0,b1).
__device__ __forceinline__ int kperm(int kx) {
    return (kx & 16) + 4 * ((kx & 7) >> 1) + ((kx >> 3) & 1) * 2 + (kx & 1);
}

// ---------------- weight conversion --------------------------------------
__global__ void convert_weights(const float* __restrict__ convs_w,
                                const float* __restrict__ in_w)
{
    long long i = (long long)blockIdx.x * 256 + threadIdx.x;
    const long long NH = 20ll * 32 * 32 * 32 * 32;
    if (i < NH) {
        int kx = (int)(i & 31); long long r = i >> 5;
        int co = (int)(r & 31); r >>= 5;
        int ky = (int)(r & 31); r >>= 5;
        int ci = (int)(r & 31); r >>= 5;
        int l  = (int)r;
        float v = convs_w[((((long long)l * 32 + co) * 32 + ci) * 32 + ky) * 32 + kx];
        __half h  = __float2half_rn(v);
        __half lo = __float2half_rn((v - __half2float(h)) * 2048.0f);
        long long ob = (long long)l * WL_HALVES
                     + ((((long long)ci * 32 + ky) * 2 + 0) * 32 + co) * 32 + kperm(kx);
        g_wcv[ob] = h;
        g_wcv[ob + 32 * 32] = lo;          // h-dim stride = 1024 halves
    } else {
        long long j = i - NH;
        if (j < 32 * 32 * 32) {
            int kx = (int)(j & 31); int rr = (int)(j >> 5);
            int co = rr & 31; rr >>= 5;
            int ky = rr & 31;
            float v = in_w[(co * 32 + ky) * 32 + kx];   // [co][1][ky][kx]
            __half h  = __float2half_rn(v);
            __half lo = __float2half_rn((v - __half2float(h)) * 2048.0f);
            long long ob = WIN_OFF + (((long long)ky * 2 + 0) * 32 + co) * 32 + kperm(kx);
            g_wcv[ob] = h;
            g_wcv[ob + 32 * 32] = lo;
        }
    }
}

// ---------------- mma helper ----------------------------------------------
__device__ __forceinline__ void mma16816(float* d, const uint32_t* a,
                                         uint32_t b0, uint32_t b1) {
    asm volatile(
        "mma.sync.aligned.m16n8k16.row.col.f32.f16.f16.f32 "
        "{%0,%1,%2,%3}, {%4,%5,%6,%7}, {%8,%9}, {%0,%1,%2,%3};"
        : "+f"(d[0]), "+f"(d[1]), "+f"(d[2]), "+f"(d[3])
        : "r"(a[0]), "r"(a[1]), "r"(a[2]), "r"(a[3]), "r"(b0), "r"(b1));
}

// ---------------- smem layout (halves) -------------------------------------
// TWO pad buffers (hi [46][96] + lo [46][96] each) for cross-ci overlap,
// then double-buffered B stage [2 buf][4 ky][2 h][32 co][48].
#define PADB_H 8832                   // halves per pad buffer
#define SB_H   17664
#define BUF_STRIDE 12288
#define SMEM_HALVES (17664 + 2 * BUF_STRIDE)
#define SMEM_SZ (SMEM_HALVES * 2)     // 84480 bytes -> 2 CTAs/SM fit

// One CTA: partial kk of out[b, :, oyh*8 .. +7, :]. M=256, N=32, K=NCI_H*1024.
// 8 warps; warp w owns oy row w (2 m-tiles sharing B). kk = blockIdx.z.
// Warp-staggered k-step order (R9); pad double-buffered: ci+1 gathered at
// mid-ci with NO trailing barrier (hidden under compute).
template <int NCI_H, int NSRC, bool RELU_IN>
__global__ __launch_bounds__(256, 2)
void mma_conv(const float* __restrict__ in,
              const __half* __restrict__ wv,
              const float* __restrict__ bias,
              float* __restrict__ out)
{
    extern __shared__ __half sh[];
    __half* sB = sh + SB_H;

    const int b = blockIdx.y, oyh = blockIdx.x, kk = blockIdx.z;
    const int t = threadIdx.x, lane = t & 31, wid = t >> 5;
    const int pr0 = oyh * 16;
    constexpr int NCI_TOT = (NCI_H == 1) ? 1 : 32;

    const __half* wvk = wv + (size_t)kk * NCI_H * 65536;
    float* outk = out + (size_t)kk * PARTIAL_OFF;

    auto load_pad_to = [&](int ci, int pb) {
        __half* dH = sh + pb * PADB_H;
        __half* dL = dH + 4416;
        const float* s0 = in + (b * NCI_TOT + ci) * 1024;
        for (int k = t; k < 46 * 94; k += 256) {
            int lr = k / 94, c = k - lr * 94;
            int off = padidx(pr0 + lr) * 32 + padidx(c);
            float v = 0.0f;
            #pragma unroll
            for (int p = 0; p < NSRC; p++) v += s0[p * PARTIAL_OFF + off];
            if (RELU_IN) v = fmaxf(v, 0.0f);
            __half h = __float2half_rn(v);
            dH[lr * 96 + c] = h;
            dL[lr * 96 + c] = __float2half_rn((v - __half2float(h)) * 2048.0f);
        }
    };

    // staging: thread t owns one (ky_l, h, co) row of 32 halves (48 stride)
    __half* st_dst0 = sB + t * 48;

    constexpr int NCHUNK = NCI_H * 8;     // 4 ky per chunk

    uint4 pf[4];
    {
        const uint4* g = (const uint4*)wvk + t * 4;
        pf[0] = g[0]; pf[1] = g[1]; pf[2] = g[2]; pf[3] = g[3];
    }
    load_pad_to(kk * NCI_H, 0);
    __syncthreads();

    float C1[32] = {}, C2[32] = {};
    const int g4 = lane >> 2, q4 = lane & 3;
    int pbuf = 0;

    for (int c = 0; c < NCHUNK; c++) {
        const int buf = c & 1;

        if (NCI_H > 1 && c > 0 && (c & 7) == 0) pbuf ^= 1;  // switch to prefetched pad

        {
            uint4* d = (uint4*)(st_dst0 + buf * BUF_STRIDE);
            d[0] = pf[0]; d[1] = pf[1]; d[2] = pf[2]; d[3] = pf[3];
        }
        if (c + 1 < NCHUNK) {
            const uint4* g = (const uint4*)wvk + (size_t)(c + 1) * 1024 + t * 4;
            pf[0] = g[0]; pf[1] = g[1]; pf[2] = g[2]; pf[3] = g[3];
        }
        __syncthreads();

        // mid-ci: gather next ci's pad into the alternate buffer. No trailing
        // barrier — each warp resumes MMAs immediately; visibility for the
        // consumer is guaranteed by the 4 staging barriers before first read,
        // and the target buffer was last read >= 4 staging barriers ago.
        if (NCI_H > 1 && (c & 7) == 4 && (c >> 3) + 1 < NCI_H)
            load_pad_to(kk * NCI_H + (c >> 3) + 1, pbuf ^ 1);

        const __half* pHc = sh + pbuf * PADB_H;
        const __half* pLc = pHc + 4416;
        const int ky0 = (c & 7) * 4;

        #pragma unroll
        for (int s0 = 0; s0 < 8; s0++) {
            const int s   = (s0 + wid) & 7;        // warp-staggered order
            const int kyl = s >> 1;
            const int kxh = (s & 1) * 16;

            const int R = 2 * wid + ky0 + kyl;
            const __half* arow = pHc + R * 96;
            const __half* lrow = pLc + R * 96;
            const __half* bky  = sB + buf * BUF_STRIDE + kyl * 3072
                               + g4 * 48 + q4 * 4;

            const int aoff = kxh + 2 * g4 + 2 * q4;
            uint32_t ah0[4], ah1[4], al0[4], al1[4];
            #pragma unroll
            for (int i = 0; i < 4; i++) {
                const int o = aoff + 16 * (i & 1) + 8 * (i >> 1);
                ah0[i] = *(const uint32_t*)(arow + o);
                ah1[i] = *(const uint32_t*)(arow + o + 32);
                al0[i] = *(const uint32_t*)(lrow + o);
                al1[i] = *(const uint32_t*)(lrow + o + 32);
            }
            const __half* bb = bky + kxh;
            uint2 bh[4], bl[4];
            #pragma unroll
            for (int nt = 0; nt < 4; nt++) {
                bh[nt] = *(const uint2*)(bb + nt * 384);          // h=0
                bl[nt] = *(const uint2*)(bb + nt * 384 + 1536);   // h=1
            }
            // 24 MMAs; same-accumulator writes >= 8 issues apart
            #pragma unroll
            for (int nt = 0; nt < 4; nt++)
                mma16816(C1 + nt * 4, ah0, bh[nt].x, bh[nt].y);
            #pragma unroll
            for (int nt = 0; nt < 4; nt++)
                mma16816(C1 + 16 + nt * 4, ah1, bh[nt].x, bh[nt].y);
            #pragma unroll
            for (int nt = 0; nt < 4; nt++)
                mma16816(C2 + nt * 4, al0, bh[nt].x, bh[nt].y);
            #pragma unroll
            for (int nt = 0; nt < 4; nt++)
                mma16816(C2 + 16 + nt * 4, al1, bh[nt].x, bh[nt].y);
            #pragma unroll
            for (int nt = 0; nt < 4; nt++)
                mma16816(C2 + nt * 4, ah0, bl[nt].x, bl[nt].y);
            #pragma unroll
            for (int nt = 0; nt < 4; nt++)
                mma16816(C2 + 16 + nt * 4, ah1, bl[nt].x, bl[nt].y);
        }
    }

    // epilogue: raw partial sums (bias only from kk==0; ReLU at consumer)
    const int oy = oyh * 8 + wid;
    const float inv = 1.0f / 2048.0f;
    const float bs = (kk == 0) ? 1.0f : 0.0f;
    #pragma unroll
    for (int mt = 0; mt < 2; mt++) {
        const int oxa = mt * 16 + g4, oxb = oxa + 8;
        #pragma unroll
        for (int nt = 0; nt < 4; nt++) {
            const int co = nt * 8 + q4 * 2;
            const int ix = mt * 16 + nt * 4;
            const float b0v = __ldg(bias + co) * bs;
            const float b1v = __ldg(bias + co + 1) * bs;
            float v00 = C1[ix+0] + C2[ix+0] * inv + b0v;
            float v01 = C1[ix+1] + C2[ix+1] * inv + b1v;
            float v10 = C1[ix+2] + C2[ix+2] * inv + b0v;
            float v11 = C1[ix+3] + C2[ix+3] * inv + b1v;
            outk[((b * 32 + co    ) * 32 + oy) * 32 + oxa] = v00;
            outk[((b * 32 + co + 1) * 32 + oy) * 32 + oxa] = v01;
            outk[((b * 32 + co    ) * 32 + oy) * 32 + oxb] = v10;
            outk[((b * 32 + co + 1) * 32 + oy) * 32 + oxb] = v11;
        }
    }
}

// Final 1x1 conv over 4-partial input (sum + ReLU fused)
__global__ void out1x1_kernel(const float* __restrict__ h,
                              const float* __restrict__ ow,
                              const float* __restrict__ ob,
                              float* __restrict__ out)
{
    const int i = blockIdx.x * blockDim.x + threadIdx.x;
    if (i >= BATCH * 1024) return;
    const int b = i >> 10;
    const int p = i & 1023;
    const float* hp = h + b * 32 * 1024 + p;
    float acc = ob[0];
    #pragma unroll
    for (int co = 0; co < 32; co++) {
        float v = hp[co * 1024] + hp[PARTIAL_OFF + co * 1024]
                + hp[2 * PARTIAL_OFF + co * 1024] + hp[3 * PARTIAL_OFF + co * 1024];
        v = fmaxf(v, 0.0f);
        acc = fmaf(v, __ldg(ow + co), acc);
    }
    out[i] = acc;
}

extern "C" void kernel_launch(void* const* d_in, const int* in_sizes, int n_in,
                              void* d_out, int out_size)
{
    const float* x       = (const float*)d_in[0];
    const float* in_w    = (const float*)d_in[1];
    const float* in_b    = (const float*)d_in[2];
    const float* convs_w = (const float*)d_in[3];
    const float* convs_b = (const float*)d_in[4];
    const float* out_w   = (const float*)d_in[5];
    const float* out_b   = (const float*)d_in[6];

    float *gin = nullptr, *gs0 = nullptr, *gs1 = nullptr;
    __half* wcv = nullptr;
    cudaGetSymbolAddress((void**)&gin, g_in);
    cudaGetSymbolAddress((void**)&gs0, g_sp0);
    cudaGetSymbolAddress((void**)&gs1, g_sp1);
    cudaGetSymbolAddress((void**)&wcv, g_wcv);

    const long long total = 20ll * 32 * 32 * 32 * 32 + 32 * 32 * 32;
    convert_weights<<<(int)((total + 255) / 256), 256>>>(convs_w, in_w);

    cudaFuncSetAttribute(mma_conv<1, 1, false>,
                         cudaFuncAttributeMaxDynamicSharedMemorySize, SMEM_SZ);
    cudaFuncSetAttribute(mma_conv<8, 1, false>,
                         cudaFuncAttributeMaxDynamicSharedMemorySize, SMEM_SZ);
    cudaFuncSetAttribute(mma_conv<8, 4, true>,
                         cudaFuncAttributeMaxDynamicSharedMemorySize, SMEM_SZ);

    // in_conv: complete (unsplit) output, no ReLU anywhere around it
    mma_conv<1, 1, false><<<dim3(4, BATCH, 1), 256, SMEM_SZ>>>(
        x, wcv + WIN_OFF, in_b, gin);

    // hidden layer 0: reads unsplit g_in (no input ReLU), writes 4-partial gs0
    mma_conv<8, 1, false><<<dim3(4, BATCH, 4), 256, SMEM_SZ>>>(
        gin, wcv, convs_b, gs0);

    // hidden layers 1..19: read 4-partial (sum+ReLU fused), write 4-partial
    float* cur = gs0;
    float* nxt = gs1;
    for (int l = 1; l < 20; l++) {
        mma_conv<8, 4, true><<<dim3(4, BATCH, 4), 256, SMEM_SZ>>>(
            cur, wcv + (size_t)l * WL_HALVES, convs_b + l * 32, nxt);
        float* tmp = cur; cur = nxt; nxt = tmp;
    }

    // 1x1 output conv (sum partials + ReLU fused)
    out1x1_kernel<<<(BATCH * 1024) / 256, 256>>>(cur, out_w, out_b, (float*)d_out);
}